// round 10
// baseline (speedup 1.0000x reference)
#include <cuda_runtime.h>
#include <cuda_fp16.h>
#include <math.h>

#define B_    32
#define IC    2048
#define OC    64
#define OD    32
#define ID    16
#define ITERS 5
#define OCD   (OC*OD)   // 2048
#define NSLOT 32
#define LOG2E 1.4426950408889634f

// Scratch (static device globals; no allocation at launch time).
// u_hat layout: [b][i][d][o] halves (p = d*64 + o).
__device__ __align__(16) __half g_uhat[(size_t)B_ * IC * OCD];   // 256 MB
__device__ float g_spart[(size_t)B_ * NSLOT * OCD];              // [b][slot][o*32+d] fp32, 8 MB
__device__ float g_V[B_ * OCD];                                  // [b][o*32+d]

__global__ void init_V(int off) {
    int idx = off + blockIdx.x * blockDim.x + threadIdx.x;
    if (idx < B_ * OCD) g_V[idx] = 0.f;
}

// ---- packed f32x2 helpers (Blackwell; ptxas won't emit from C++) ----
__device__ __forceinline__ unsigned long long pk2(float a, float b) {
    unsigned long long r;
    asm("mov.b64 %0, {%1, %2};" : "=l"(r) : "f"(a), "f"(b));
    return r;
}
__device__ __forceinline__ unsigned long long fma2(unsigned long long a,
                                                   unsigned long long b,
                                                   unsigned long long c) {
    unsigned long long r;
    asm("fma.rn.f32x2 %0, %1, %2, %3;" : "=l"(r) : "l"(a), "l"(b), "l"(c));
    return r;
}
__device__ __forceinline__ unsigned long long add2(unsigned long long a,
                                                   unsigned long long b) {
    unsigned long long r;
    asm("add.rn.f32x2 %0, %1, %2;" : "=l"(r) : "l"(a), "l"(b));
    return r;
}
__device__ __forceinline__ unsigned long long mul2(unsigned long long a,
                                                   unsigned long long b) {
    unsigned long long r;
    asm("mul.rn.f32x2 %0, %1, %2;" : "=l"(r) : "l"(a), "l"(b));
    return r;
}
__device__ __forceinline__ float2 unpk2(unsigned long long v) {
    float2 f;
    asm("mov.b64 {%0, %1}, %2;" : "=f"(f.x), "=f"(f.y) : "l"(v));
    return f;
}
__device__ __forceinline__ float ex2(float x) {
    float r;
    asm("ex2.approx.f32 %0, %1;" : "=f"(r) : "f"(x));
    return r;
}

// Pass A: u_hat[b,i,d,o] = sum_k W[i,o,d,k] * x[b,i,k], fp16 store, layout [d][o].
__global__ __launch_bounds__(256) void uhat_kernel(const float* __restrict__ x,
                                                   const float* __restrict__ W) {
    int i = blockIdx.x;
    int t = threadIdx.x;
    int w = t >> 5, l = t & 31;
    __shared__ __align__(16) unsigned long long xs2[B_][ID];   // (xk, xk)
    for (int idx = t; idx < B_ * ID; idx += 256) {
        int b = idx >> 4, k = idx & 15;
        float xv = x[((size_t)b * IC + i) * ID + k];
        xs2[b][k] = pk2(xv, xv);
    }
    __syncthreads();

#pragma unroll
    for (int j = 0; j < 4; j++) {
        int d = 8 * j + w;
        int o0 = 2 * l;
        const float4* w0p = (const float4*)(W + ((size_t)i * OCD + (size_t)o0 * OD + d) * ID);
        const float4* w1p = (const float4*)(W + ((size_t)i * OCD + (size_t)(o0 + 1) * OD + d) * ID);

        unsigned long long wp[ID];
#pragma unroll
        for (int c = 0; c < 4; c++) {
            float4 a = w0p[c], bb = w1p[c];
            wp[4 * c + 0] = pk2(a.x, bb.x);
            wp[4 * c + 1] = pk2(a.y, bb.y);
            wp[4 * c + 2] = pk2(a.z, bb.z);
            wp[4 * c + 3] = pk2(a.w, bb.w);
        }

        for (int b = 0; b < B_; b++) {
            const ulonglong2* xp = (const ulonglong2*)xs2[b];
            unsigned long long acc = 0ull;
#pragma unroll
            for (int kk = 0; kk < 8; kk++) {
                ulonglong2 xv = xp[kk];
                acc = fma2(wp[2 * kk],     xv.x, acc);
                acc = fma2(wp[2 * kk + 1], xv.y, acc);
            }
            float2 u = unpk2(acc);
            size_t base = ((size_t)b * IC + i) * OCD;
            *(__half2*)(g_uhat + base + (size_t)d * OC + o0) = __floats2half2_rn(u.x, u.y);
        }
    }
}

__device__ __forceinline__ __half2 h2shfl_xor(__half2 v, int m) {
    unsigned int u = *(unsigned int*)&v;
    u = __shfl_xor_sync(0xffffffffu, u, m);
    return *(__half2*)&u;
}

// Routing pass v6 — fp32 exp path (R8 numerics) with packed f32x2 ALU.
// Grid (32 chunks, 32 b), 128 thr (4 warps). Chunk = 64 i's.
// Warp w owns d-range [8w, 8w+8); lane l: d8 = l>>2, oq = l&3; d = 8w + d8.
// Thread covers o in [16*oq, 16*oq+16). m/Z combined over o-quarters via shfl 1,2.
// max pass in half2 (softmax-exact); logits/exp/Z/acc all fp32 (f32x2-packed).
__global__ __launch_bounds__(128, 6) void routing_kernel() {
    int chunk = blockIdx.x;
    int b = blockIdx.y;
    int t = threadIdx.x;
    int w = t >> 5, l = t & 31;
    int d8 = l >> 2, oq = l & 3;
    int d = w * 8 + d8;

    __shared__ float sbuf[OCD];    // 8 KB: V staging first, then partial staging
    for (int idx = t; idx < OCD; idx += 128) sbuf[idx] = g_V[b * OCD + idx];
    __syncthreads();

    __half2 Vh[8];                 // half2 V (scaled) for the max pass
    unsigned long long Vp[8];      // f32x2 V (scaled) for the exp pass
#pragma unroll
    for (int q = 0; q < 8; q++) {
        int o = oq * 16 + 2 * q;
        float v0 = sbuf[o * OD + d] * LOG2E;
        float v1 = sbuf[(o + 1) * OD + d] * LOG2E;
        Vh[q] = __floats2half2_rn(v0, v1);
        Vp[q] = pk2(v0, v1);
    }
    __syncthreads();   // sbuf reused for output staging below

    unsigned long long accp[8];
#pragma unroll
    for (int q = 0; q < 8; q++) accp[q] = 0ull;   // (0.f, 0.f)

    for (int ii = 0; ii < 64; ii++) {
        int i = chunk * 64 + ii;
        const uint4* up = (const uint4*)(g_uhat + ((size_t)b * IC + i) * OCD
                                         + (size_t)d * OC + oq * 16);
        uint4 r0 = up[0], r1 = up[1];
        unsigned int Ur[8] = {r0.x, r0.y, r0.z, r0.w, r1.x, r1.y, r1.z, r1.w};
        __half2* U = (__half2*)Ur;

        // max pass in half2; any m <= true max just loses nothing (softmax-invariant)
        __half2 mh = __float2half2_rn(-60000.f);
#pragma unroll
        for (int q = 0; q < 8; q++)
            mh = __hmax2(mh, __hmul2(U[q], Vh[q]));
        mh = __hmax2(mh, h2shfl_xor(mh, 1));
        mh = __hmax2(mh, h2shfl_xor(mh, 2));
        mh = __hmax2(mh, __lowhigh2highlow(mh));
        float m = __low2float(mh);
        unsigned long long negm = pk2(-m, -m);

        // exp pass: fp32 logits via FFMA2, scalar MUFU ex2, packed Z and u*e
        unsigned long long Zp = 0ull;
        unsigned long long P[8];
#pragma unroll
        for (int q = 0; q < 8; q++) {
            float2 uf = __half22float2(U[q]);
            unsigned long long ufp = pk2(uf.x, uf.y);
            float2 lf = unpk2(fma2(ufp, Vp[q], negm));
            unsigned long long ep = pk2(ex2(lf.x), ex2(lf.y));
            Zp = add2(Zp, ep);
            P[q] = mul2(ufp, ep);
        }
        float2 zf = unpk2(Zp);
        float Z = zf.x + zf.y;
        Z += __shfl_xor_sync(0xffffffffu, Z, 1);
        Z += __shfl_xor_sync(0xffffffffu, Z, 2);
        float rZ = __fdividef(1.0f, Z);
        unsigned long long rz2 = pk2(rZ, rZ);
#pragma unroll
        for (int q = 0; q < 8; q++)
            accp[q] = fma2(P[q], rz2, accp[q]);
    }

#pragma unroll
    for (int q = 0; q < 8; q++) {
        float2 a = unpk2(accp[q]);
        int o = oq * 16 + 2 * q;
        sbuf[o * OD + d]       = a.x;
        sbuf[(o + 1) * OD + d] = a.y;
    }
    __syncthreads();

    // coalesced store of the CTA partial
    float* sp = g_spart + ((size_t)(b * NSLOT + chunk)) * OCD;
#pragma unroll
    for (int r = 0; r < 16; r++) {
        int p = t + 128 * r;
        sp[p] = sbuf[p];
    }
}

// Reduce 32 fp32 slots, squash over d, update V (+ output on last iter).
__global__ __launch_bounds__(128) void update_kernel(float* __restrict__ out, int is_last) {
    int bo = blockIdx.x;       // 0..2047
    int b = bo >> 6, o = bo & 63;
    int t = threadIdx.x;
    int g = t >> 5, d = t & 31;

    float s = 0.f;
#pragma unroll
    for (int k = 0; k < 8; k++)
        s += g_spart[((size_t)(b * NSLOT + g + 4 * k)) * OCD + o * OD + d];

    __shared__ float red[4][OD];
    red[g][d] = s;
    __syncthreads();

    if (t < 32) {
        float tot = red[0][d] + red[1][d] + red[2][d] + red[3][d];
        float n2 = tot * tot;
#pragma unroll
        for (int k = 16; k > 0; k >>= 1) n2 += __shfl_xor_sync(0xffffffffu, n2, k);
        float factor = n2 / ((1.f + n2) * sqrtf(n2 + 1e-8f));
        float v = factor * tot;
        g_V[b * OCD + o * OD + d] += v;
        if (is_last) out[((size_t)b * OC + o) * OD + d] = v;
    }
}

extern "C" void kernel_launch(void* const* d_in, const int* in_sizes, int n_in,
                              void* d_out, int out_size) {
    const float* x = (const float*)d_in[0];
    const float* W = (const float*)d_in[1];
    if (n_in >= 2 && in_sizes[0] > in_sizes[1]) {  // defensive: x is the smaller input
        const float* tmp = x; x = W; W = tmp;
    }
    float* out = (float*)d_out;

    // 5 idempotent init launches: zero V (twice over) AND place uhat_kernel at
    // launch index 5 so ncu (-s 5 -c 1) profiles uhat this round.
    init_V<<<128, 256>>>(0);
    init_V<<<128, 256>>>(32768);
    init_V<<<128, 256>>>(0);
    init_V<<<128, 256>>>(32768);
    init_V<<<128, 256>>>(0);
    uhat_kernel<<<IC, 256>>>(x, W);
    for (int r = 0; r < ITERS; r++) {
        routing_kernel<<<dim3(NSLOT, B_), 128>>>();
        update_kernel<<<B_ * OC, 128>>>(out, r == ITERS - 1);
    }
}

// round 11
// speedup vs baseline: 1.0150x; 1.0150x over previous
#include <cuda_runtime.h>
#include <cuda_fp16.h>
#include <math.h>

#define B_    32
#define IC    2048
#define OC    64
#define OD    32
#define ID    16
#define ITERS 5
#define OCD   (OC*OD)   // 2048
#define NSLOT 32
#define LOG2E 1.4426950408889634f

// Scratch (static device globals; no allocation at launch time).
// u_hat layout: [b][i][d][o] halves (p = d*64 + o).
__device__ __align__(16) __half g_uhat[(size_t)B_ * IC * OCD];   // 256 MB
__device__ float g_spart[(size_t)B_ * NSLOT * OCD];              // [b][slot][o*32+d] fp32, 8 MB
__device__ float g_V[B_ * OCD];                                  // [b][o*32+d]

__global__ void init_V(int off) {
    int idx = off + blockIdx.x * blockDim.x + threadIdx.x;
    if (idx < B_ * OCD) g_V[idx] = 0.f;
}

// ---- packed f32x2 helpers (Blackwell; ptxas won't emit from C++) ----
__device__ __forceinline__ unsigned long long pk2(float a, float b) {
    unsigned long long r;
    asm("mov.b64 %0, {%1, %2};" : "=l"(r) : "f"(a), "f"(b));
    return r;
}
__device__ __forceinline__ unsigned long long fma2(unsigned long long a,
                                                   unsigned long long b,
                                                   unsigned long long c) {
    unsigned long long r;
    asm("fma.rn.f32x2 %0, %1, %2, %3;" : "=l"(r) : "l"(a), "l"(b), "l"(c));
    return r;
}
__device__ __forceinline__ float2 unpk2(unsigned long long v) {
    float2 f;
    asm("mov.b64 {%0, %1}, %2;" : "=f"(f.x), "=f"(f.y) : "l"(v));
    return f;
}
__device__ __forceinline__ float ex2(float x) {
    float r;
    asm("ex2.approx.f32 %0, %1;" : "=f"(r) : "f"(x));
    return r;
}
__device__ __forceinline__ float rcpf(float x) {
    float r;
    asm("rcp.approx.f32 %0, %1;" : "=f"(r) : "f"(x));
    return r;
}

// Pass A v2: u_hat[b,i,d,o] = sum_k W[i,o,d,k] * x[b,i,k], fp16 store, layout [d][o].
// CTA per i. j=0..1: thread owns 4 W rows: (o0,d0),(o0+1,d0),(o0,d1),(o0+1,d1)
// with d0 = 8j+w (0..15), d1 = d0+16, o0 = 2l. One x LDS stream feeds all 4 rows.
__global__ __launch_bounds__(256) void uhat_kernel(const float* __restrict__ x,
                                                   const float* __restrict__ W) {
    int i = blockIdx.x;
    int t = threadIdx.x;
    int w = t >> 5, l = t & 31;
    __shared__ __align__(16) unsigned long long xs2[B_][ID];   // (xk, xk)
    for (int idx = t; idx < B_ * ID; idx += 256) {
        int b = idx >> 4, k = idx & 15;
        float xv = x[((size_t)b * IC + i) * ID + k];
        xs2[b][k] = pk2(xv, xv);
    }
    __syncthreads();

#pragma unroll
    for (int j = 0; j < 2; j++) {
        int d0 = 8 * j + w;
        int d1 = d0 + 16;
        int o0 = 2 * l;
        const float4* wa0 = (const float4*)(W + ((size_t)i * OCD + (size_t)o0 * OD + d0) * ID);
        const float4* wa1 = (const float4*)(W + ((size_t)i * OCD + (size_t)(o0 + 1) * OD + d0) * ID);
        const float4* wb0 = (const float4*)(W + ((size_t)i * OCD + (size_t)o0 * OD + d1) * ID);
        const float4* wb1 = (const float4*)(W + ((size_t)i * OCD + (size_t)(o0 + 1) * OD + d1) * ID);

        unsigned long long wpA[ID], wpB[ID];
#pragma unroll
        for (int c = 0; c < 4; c++) {
            float4 a0 = wa0[c], a1 = wa1[c];
            wpA[4 * c + 0] = pk2(a0.x, a1.x);
            wpA[4 * c + 1] = pk2(a0.y, a1.y);
            wpA[4 * c + 2] = pk2(a0.z, a1.z);
            wpA[4 * c + 3] = pk2(a0.w, a1.w);
            float4 b0 = wb0[c], b1 = wb1[c];
            wpB[4 * c + 0] = pk2(b0.x, b1.x);
            wpB[4 * c + 1] = pk2(b0.y, b1.y);
            wpB[4 * c + 2] = pk2(b0.z, b1.z);
            wpB[4 * c + 3] = pk2(b0.w, b1.w);
        }

        for (int b = 0; b < B_; b++) {
            const ulonglong2* xp = (const ulonglong2*)xs2[b];
            unsigned long long accA = 0ull, accB = 0ull;   // (0.f, 0.f)
#pragma unroll
            for (int kk = 0; kk < 8; kk++) {
                ulonglong2 xv = xp[kk];
                accA = fma2(wpA[2 * kk],     xv.x, accA);
                accA = fma2(wpA[2 * kk + 1], xv.y, accA);
                accB = fma2(wpB[2 * kk],     xv.x, accB);
                accB = fma2(wpB[2 * kk + 1], xv.y, accB);
            }
            float2 uA = unpk2(accA), uB = unpk2(accB);
            size_t base = ((size_t)b * IC + i) * OCD;
            *(__half2*)(g_uhat + base + (size_t)d0 * OC + o0) = __floats2half2_rn(uA.x, uA.y);
            *(__half2*)(g_uhat + base + (size_t)d1 * OC + o0) = __floats2half2_rn(uB.x, uB.y);
        }
    }
}

__device__ __forceinline__ __half2 h2shfl_xor(__half2 v, int m) {
    unsigned int u = *(unsigned int*)&v;
    u = __shfl_xor_sync(0xffffffffu, u, m);
    return *(__half2*)&u;
}

// Routing pass v7 — R8 structure; fp32 P stash (no half2 round-trip), V in regs.
// Grid (32 chunks, 32 b), 128 thr (4 warps). Chunk = 64 i's.
// Warp w owns d-range [8w, 8w+8); lane l: d8 = l>>2, oq = l&3; d = 8w + d8.
// Thread covers o in [16*oq, 16*oq+16). m/Z combined over o-quarters via shfl 1,2.
__global__ __launch_bounds__(128, 6) void routing_kernel() {
    int chunk = blockIdx.x;
    int b = blockIdx.y;
    int t = threadIdx.x;
    int w = t >> 5, l = t & 31;
    int d8 = l >> 2, oq = l & 3;
    int d = w * 8 + d8;

    __shared__ float sbuf[OCD];    // 8 KB: V staging, then output staging
    for (int idx = t; idx < OCD; idx += 128) sbuf[idx] = g_V[b * OCD + idx];
    __syncthreads();

    __half2 Vh[8];     // half2 V (scaled by log2e) for the max pass
    float2  Vp[8];     // fp32 V (scaled) for the logit FFMA
#pragma unroll
    for (int q = 0; q < 8; q++) {
        int o = oq * 16 + 2 * q;
        float v0 = sbuf[o * OD + d] * LOG2E;
        float v1 = sbuf[(o + 1) * OD + d] * LOG2E;
        Vh[q] = __floats2half2_rn(v0, v1);
        Vp[q] = make_float2(v0, v1);
    }
    __syncthreads();   // sbuf reused for output staging below

    float acc[16];
#pragma unroll
    for (int j = 0; j < 16; j++) acc[j] = 0.f;

    for (int ii = 0; ii < 64; ii++) {
        int i = chunk * 64 + ii;
        const uint4* up = (const uint4*)(g_uhat + ((size_t)b * IC + i) * OCD
                                         + (size_t)d * OC + oq * 16);
        uint4 r0 = up[0], r1 = up[1];
        unsigned int Ur[8] = {r0.x, r0.y, r0.z, r0.w, r1.x, r1.y, r1.z, r1.w};
        __half2* U = (__half2*)Ur;

        // max pass in half2 (any m >= true max is softmax-exact; rounding-up is safe)
        __half2 mh = __float2half2_rn(-60000.f);
#pragma unroll
        for (int q = 0; q < 8; q++)
            mh = __hmax2(mh, __hmul2(U[q], Vh[q]));
        mh = __hmax2(mh, h2shfl_xor(mh, 1));
        mh = __hmax2(mh, h2shfl_xor(mh, 2));
        mh = __hmax2(mh, __lowhigh2highlow(mh));
        float m = __low2float(mh);

        // exp pass: fp32 logits, MUFU ex2; stash u*e in fp32 P (no reconvert)
        float P[16];
        float Z = 0.f;
#pragma unroll
        for (int q = 0; q < 8; q++) {
            float2 uf = __half22float2(U[q]);
            float e0 = ex2(fmaf(uf.x, Vp[q].x, -m));
            float e1 = ex2(fmaf(uf.y, Vp[q].y, -m));
            Z += e0 + e1;
            P[2 * q]     = uf.x * e0;
            P[2 * q + 1] = uf.y * e1;
        }
        Z += __shfl_xor_sync(0xffffffffu, Z, 1);
        Z += __shfl_xor_sync(0xffffffffu, Z, 2);
        float rZ = rcpf(Z);
#pragma unroll
        for (int j = 0; j < 16; j++)
            acc[j] = fmaf(P[j], rZ, acc[j]);
    }

#pragma unroll
    for (int j = 0; j < 16; j++)
        sbuf[(oq * 16 + j) * OD + d] = acc[j];
    __syncthreads();

    // coalesced store of the CTA partial
    float* sp = g_spart + ((size_t)(b * NSLOT + chunk)) * OCD;
#pragma unroll
    for (int r = 0; r < 16; r++) {
        int p = t + 128 * r;
        sp[p] = sbuf[p];
    }
}

// Reduce 32 fp32 slots, squash over d, update V (+ output on last iter).
__global__ __launch_bounds__(128) void update_kernel(float* __restrict__ out, int is_last) {
    int bo = blockIdx.x;       // 0..2047
    int b = bo >> 6, o = bo & 63;
    int t = threadIdx.x;
    int g = t >> 5, d = t & 31;

    float s = 0.f;
#pragma unroll
    for (int k = 0; k < 8; k++)
        s += g_spart[((size_t)(b * NSLOT + g + 4 * k)) * OCD + o * OD + d];

    __shared__ float red[4][OD];
    red[g][d] = s;
    __syncthreads();

    if (t < 32) {
        float tot = red[0][d] + red[1][d] + red[2][d] + red[3][d];
        float n2 = tot * tot;
#pragma unroll
        for (int k = 16; k > 0; k >>= 1) n2 += __shfl_xor_sync(0xffffffffu, n2, k);
        float factor = n2 / ((1.f + n2) * sqrtf(n2 + 1e-8f));
        float v = factor * tot;
        g_V[b * OCD + o * OD + d] += v;
        if (is_last) out[((size_t)b * OC + o) * OD + d] = v;
    }
}

extern "C" void kernel_launch(void* const* d_in, const int* in_sizes, int n_in,
                              void* d_out, int out_size) {
    const float* x = (const float*)d_in[0];
    const float* W = (const float*)d_in[1];
    if (n_in >= 2 && in_sizes[0] > in_sizes[1]) {  // defensive: x is the smaller input
        const float* tmp = x; x = W; W = tmp;
    }
    float* out = (float*)d_out;

    // launches: init(0), init(1), uhat(2), routing(3), update(4), routing(5)...
    // ncu -s 5 -c 1 captures routing #2.
    init_V<<<128, 256>>>(0);
    init_V<<<128, 256>>>(32768);
    uhat_kernel<<<IC, 256>>>(x, W);
    for (int r = 0; r < ITERS; r++) {
        routing_kernel<<<dim3(NSLOT, B_), 128>>>();
        update_kernel<<<B_ * OC, 128>>>(out, r == ITERS - 1);
    }
}

// round 12
// speedup vs baseline: 1.3878x; 1.3673x over previous
#include <cuda_runtime.h>
#include <cuda_fp16.h>
#include <math.h>

#define B_    32
#define IC    2048
#define OC    64
#define OD    32
#define ID    16
#define ITERS 5
#define OCD   (OC*OD)   // 2048
#define NSLOT 32
#define LOG2E 1.4426950408889634f

// Scratch (static device globals; no allocation at launch time).
// u_hat layout: [b][i][d][o] halves (p = d*64 + o).
__device__ __align__(16) __half g_uhat[(size_t)B_ * IC * OCD];   // 256 MB
__device__ float g_spart[(size_t)B_ * NSLOT * OCD];              // [b][slot][o*32+d] fp32, 8 MB
__device__ float g_V[B_ * OCD];                                  // [b][o*32+d]

__global__ void init_V(int off) {
    int idx = off + blockIdx.x * blockDim.x + threadIdx.x;
    if (idx < B_ * OCD) g_V[idx] = 0.f;
}

// ---- packed f32x2 helpers (Blackwell; ptxas won't emit from C++) ----
__device__ __forceinline__ unsigned long long pk2(float a, float b) {
    unsigned long long r;
    asm("mov.b64 %0, {%1, %2};" : "=l"(r) : "f"(a), "f"(b));
    return r;
}
__device__ __forceinline__ unsigned long long fma2(unsigned long long a,
                                                   unsigned long long b,
                                                   unsigned long long c) {
    unsigned long long r;
    asm("fma.rn.f32x2 %0, %1, %2, %3;" : "=l"(r) : "l"(a), "l"(b), "l"(c));
    return r;
}
__device__ __forceinline__ float2 unpk2(unsigned long long v) {
    float2 f;
    asm("mov.b64 {%0, %1}, %2;" : "=f"(f.x), "=f"(f.y) : "l"(v));
    return f;
}
__device__ __forceinline__ float ex2(float x) {
    float r;
    asm("ex2.approx.f32 %0, %1;" : "=f"(r) : "f"(x));
    return r;
}

// Pass A v2 (kept from R11, ~122us): u_hat[b,i,d,o], fp16 store, layout [d][o].
// CTA per i. Thread owns 4 W rows; one x LDS stream feeds all 4.
__global__ __launch_bounds__(256) void uhat_kernel(const float* __restrict__ x,
                                                   const float* __restrict__ W) {
    int i = blockIdx.x;
    int t = threadIdx.x;
    int w = t >> 5, l = t & 31;
    __shared__ __align__(16) unsigned long long xs2[B_][ID];   // (xk, xk)
    for (int idx = t; idx < B_ * ID; idx += 256) {
        int b = idx >> 4, k = idx & 15;
        float xv = x[((size_t)b * IC + i) * ID + k];
        xs2[b][k] = pk2(xv, xv);
    }
    __syncthreads();

#pragma unroll
    for (int j = 0; j < 2; j++) {
        int d0 = 8 * j + w;
        int d1 = d0 + 16;
        int o0 = 2 * l;
        const float4* wa0 = (const float4*)(W + ((size_t)i * OCD + (size_t)o0 * OD + d0) * ID);
        const float4* wa1 = (const float4*)(W + ((size_t)i * OCD + (size_t)(o0 + 1) * OD + d0) * ID);
        const float4* wb0 = (const float4*)(W + ((size_t)i * OCD + (size_t)o0 * OD + d1) * ID);
        const float4* wb1 = (const float4*)(W + ((size_t)i * OCD + (size_t)(o0 + 1) * OD + d1) * ID);

        unsigned long long wpA[ID], wpB[ID];
#pragma unroll
        for (int c = 0; c < 4; c++) {
            float4 a0 = wa0[c], a1 = wa1[c];
            wpA[4 * c + 0] = pk2(a0.x, a1.x);
            wpA[4 * c + 1] = pk2(a0.y, a1.y);
            wpA[4 * c + 2] = pk2(a0.z, a1.z);
            wpA[4 * c + 3] = pk2(a0.w, a1.w);
            float4 b0 = wb0[c], b1 = wb1[c];
            wpB[4 * c + 0] = pk2(b0.x, b1.x);
            wpB[4 * c + 1] = pk2(b0.y, b1.y);
            wpB[4 * c + 2] = pk2(b0.z, b1.z);
            wpB[4 * c + 3] = pk2(b0.w, b1.w);
        }

        for (int b = 0; b < B_; b++) {
            const ulonglong2* xp = (const ulonglong2*)xs2[b];
            unsigned long long accA = 0ull, accB = 0ull;   // (0.f, 0.f)
#pragma unroll
            for (int kk = 0; kk < 8; kk++) {
                ulonglong2 xv = xp[kk];
                accA = fma2(wpA[2 * kk],     xv.x, accA);
                accA = fma2(wpA[2 * kk + 1], xv.y, accA);
                accB = fma2(wpB[2 * kk],     xv.x, accB);
                accB = fma2(wpB[2 * kk + 1], xv.y, accB);
            }
            float2 uA = unpk2(accA), uB = unpk2(accB);
            size_t base = ((size_t)b * IC + i) * OCD;
            *(__half2*)(g_uhat + base + (size_t)d0 * OC + o0) = __floats2half2_rn(uA.x, uA.y);
            *(__half2*)(g_uhat + base + (size_t)d1 * OC + o0) = __floats2half2_rn(uB.x, uB.y);
        }
    }
}

__device__ __forceinline__ __half2 h2shfl_xor(__half2 v, int m) {
    unsigned int u = *(unsigned int*)&v;
    u = __shfl_xor_sync(0xffffffffu, u, m);
    return *(__half2*)&u;
}

// Iteration 0: V = 0 -> softmax is exactly uniform (c = 1/64). Plain partial sum.
__global__ __launch_bounds__(128, 8) void routing0_kernel() {
    int chunk = blockIdx.x;
    int b = blockIdx.y;
    int t = threadIdx.x;
    int w = t >> 5, l = t & 31;
    int d8 = l >> 2, oq = l & 3;
    int d = w * 8 + d8;

    float acc[16];
#pragma unroll
    for (int j = 0; j < 16; j++) acc[j] = 0.f;

    for (int ii = 0; ii < 64; ii++) {
        int i = chunk * 64 + ii;
        const uint4* up = (const uint4*)(g_uhat + ((size_t)b * IC + i) * OCD
                                         + (size_t)d * OC + oq * 16);
        uint4 r0 = up[0], r1 = up[1];
        unsigned int Ur[8] = {r0.x, r0.y, r0.z, r0.w, r1.x, r1.y, r1.z, r1.w};
#pragma unroll
        for (int q = 0; q < 8; q++) {
            float2 uf = __half22float2(((__half2*)Ur)[q]);
            acc[2 * q]     += uf.x;
            acc[2 * q + 1] += uf.y;
        }
    }

    __shared__ float sbuf[OCD];
#pragma unroll
    for (int j = 0; j < 16; j++)
        sbuf[(oq * 16 + j) * OD + d] = acc[j] * (1.0f / 64.0f);
    __syncthreads();

    float* sp = g_spart + ((size_t)(b * NSLOT + chunk)) * OCD;
#pragma unroll
    for (int r = 0; r < 16; r++) {
        int p = t + 128 * r;
        sp[p] = sbuf[p];
    }
}

// Routing (iters 1..4) — exact R8 structure; V in smem as two swizzled float
// planes (conflict-free LDS.32), half2 stash, fp32 exp/Z/acc. regs ~64, 8 CTA/SM.
// Grid (32 chunks, 32 b), 128 thr. Warp w owns d in [8w,8w+8); lane: d8=l>>2, oq=l&3.
__global__ __launch_bounds__(128, 8) void routing_kernel() {
    int chunk = blockIdx.x;
    int b = blockIdx.y;
    int t = threadIdx.x;
    int w = t >> 5, l = t & 31;
    int d8 = l >> 2, oq = l & 3;
    int d = w * 8 + d8;

    // Vx plane [0..1024), Vy plane [1024..2048); column swizzled by (dd + 8*(row>>3)) & 31
    __shared__ float Vs[OCD];        // 8 KB, live through the main loop
    __shared__ float stage[OCD];     // 8 KB output staging
    for (int idx = t; idx < 1024; idx += 128) {
        int q = idx >> 5, dd = idx & 31;
        int swc = (dd + 8 * (q >> 3)) & 31;
        Vs[q * 32 + swc]        = g_V[b * OCD + (2 * q) * OD + dd] * LOG2E;
        Vs[1024 + q * 32 + swc] = g_V[b * OCD + (2 * q + 1) * OD + dd] * LOG2E;
    }
    __syncthreads();

    int swc = (d + 8 * oq) & 31;
    __half2 Vh[8];
#pragma unroll
    for (int q = 0; q < 8; q++) {
        int row = oq * 8 + q;
        Vh[q] = __floats2half2_rn(Vs[row * 32 + swc], Vs[1024 + row * 32 + swc]);
    }

    float acc[16];
#pragma unroll
    for (int j = 0; j < 16; j++) acc[j] = 0.f;

    for (int ii = 0; ii < 64; ii++) {
        int i = chunk * 64 + ii;
        const uint4* up = (const uint4*)(g_uhat + ((size_t)b * IC + i) * OCD
                                         + (size_t)d * OC + oq * 16);
        uint4 r0 = up[0], r1 = up[1];
        unsigned int Ur[8] = {r0.x, r0.y, r0.z, r0.w, r1.x, r1.y, r1.z, r1.w};
        __half2* U = (__half2*)Ur;

        // max pass in half2 (any m >= per-i max is softmax-exact)
        __half2 mh = __float2half2_rn(-60000.f);
#pragma unroll
        for (int q = 0; q < 8; q++)
            mh = __hmax2(mh, __hmul2(U[q], Vh[q]));
        mh = __hmax2(mh, h2shfl_xor(mh, 1));
        mh = __hmax2(mh, h2shfl_xor(mh, 2));
        mh = __hmax2(mh, __lowhigh2highlow(mh));
        float m = __low2float(mh);

        // exp pass: fp32 logits from swizzled smem V, MUFU ex2; stash u*e as half2
        float Z = 0.f;
#pragma unroll
        for (int q = 0; q < 8; q++) {
            int row = oq * 8 + q;
            float2 uf = __half22float2(U[q]);
            float e0 = ex2(fmaf(uf.x, Vs[row * 32 + swc], -m));
            float e1 = ex2(fmaf(uf.y, Vs[1024 + row * 32 + swc], -m));
            Z += e0 + e1;
            __half2 th = __floats2half2_rn(uf.x * e0, uf.y * e1);
            U[q] = th;
        }
        Z += __shfl_xor_sync(0xffffffffu, Z, 1);
        Z += __shfl_xor_sync(0xffffffffu, Z, 2);
        float rZ = __fdividef(1.0f, Z);
#pragma unroll
        for (int q = 0; q < 8; q++) {
            float2 tf = __half22float2(U[q]);
            acc[2 * q]     = fmaf(tf.x, rZ, acc[2 * q]);
            acc[2 * q + 1] = fmaf(tf.y, rZ, acc[2 * q + 1]);
        }
    }

#pragma unroll
    for (int j = 0; j < 16; j++)
        stage[(oq * 16 + j) * OD + d] = acc[j];
    __syncthreads();

    // coalesced store of the CTA partial
    float* sp = g_spart + ((size_t)(b * NSLOT + chunk)) * OCD;
#pragma unroll
    for (int r = 0; r < 16; r++) {
        int p = t + 128 * r;
        sp[p] = stage[p];
    }
}

// Reduce 32 fp32 slots, squash over d, update V (+ output on last iter).
__global__ __launch_bounds__(128) void update_kernel(float* __restrict__ out, int is_last) {
    int bo = blockIdx.x;       // 0..2047
    int b = bo >> 6, o = bo & 63;
    int t = threadIdx.x;
    int g = t >> 5, d = t & 31;

    float s = 0.f;
#pragma unroll
    for (int k = 0; k < 8; k++)
        s += g_spart[((size_t)(b * NSLOT + g + 4 * k)) * OCD + o * OD + d];

    __shared__ float red[4][OD];
    red[g][d] = s;
    __syncthreads();

    if (t < 32) {
        float tot = red[0][d] + red[1][d] + red[2][d] + red[3][d];
        float n2 = tot * tot;
#pragma unroll
        for (int k = 16; k > 0; k >>= 1) n2 += __shfl_xor_sync(0xffffffffu, n2, k);
        float factor = n2 / ((1.f + n2) * sqrtf(n2 + 1e-8f));
        float v = factor * tot;
        g_V[b * OCD + o * OD + d] += v;
        if (is_last) out[((size_t)b * OC + o) * OD + d] = v;
    }
}

extern "C" void kernel_launch(void* const* d_in, const int* in_sizes, int n_in,
                              void* d_out, int out_size) {
    const float* x = (const float*)d_in[0];
    const float* W = (const float*)d_in[1];
    if (n_in >= 2 && in_sizes[0] > in_sizes[1]) {  // defensive: x is the smaller input
        const float* tmp = x; x = W; W = tmp;
    }
    float* out = (float*)d_out;

    // launches: 0 init, 1 init, 2 uhat, 3 routing0, 4 update, 5 routing <- ncu -s 5
    init_V<<<128, 256>>>(0);
    init_V<<<128, 256>>>(32768);
    uhat_kernel<<<IC, 256>>>(x, W);
    routing0_kernel<<<dim3(NSLOT, B_), 128>>>();
    update_kernel<<<B_ * OC, 128>>>(out, 0);
    for (int r = 1; r < ITERS; r++) {
        routing_kernel<<<dim3(NSLOT, B_), 128>>>();
        update_kernel<<<B_ * OC, 128>>>(out, r == ITERS - 1);
    }
}

// round 13
// speedup vs baseline: 1.3886x; 1.0006x over previous
#include <cuda_runtime.h>
#include <cuda_fp16.h>
#include <math.h>

#define B_    32
#define IC    2048
#define OC    64
#define OD    32
#define ID    16
#define ITERS 5
#define OCD   (OC*OD)   // 2048
#define NSLOT 32
#define LOG2E 1.4426950408889634f

// Scratch (static device globals; no allocation at launch time).
// u_hat layout: [b][i][d][o] halves (p = d*64 + o).
__device__ __align__(16) __half g_uhat[(size_t)B_ * IC * OCD];   // 256 MB
__device__ float g_spart[(size_t)B_ * NSLOT * OCD];              // [b][slot][o*32+d] fp32, 8 MB
__device__ float g_V[B_ * OCD];                                  // [b][o*32+d]

__global__ void init_V(int off) {
    int idx = off + blockIdx.x * blockDim.x + threadIdx.x;
    if (idx < B_ * OCD) g_V[idx] = 0.f;
}

// ---- packed f32x2 helpers (Blackwell; ptxas won't emit from C++) ----
__device__ __forceinline__ unsigned long long pk2(float a, float b) {
    unsigned long long r;
    asm("mov.b64 %0, {%1, %2};" : "=l"(r) : "f"(a), "f"(b));
    return r;
}
__device__ __forceinline__ unsigned long long fma2(unsigned long long a,
                                                   unsigned long long b,
                                                   unsigned long long c) {
    unsigned long long r;
    asm("fma.rn.f32x2 %0, %1, %2, %3;" : "=l"(r) : "l"(a), "l"(b), "l"(c));
    return r;
}
__device__ __forceinline__ float2 unpk2(unsigned long long v) {
    float2 f;
    asm("mov.b64 {%0, %1}, %2;" : "=f"(f.x), "=f"(f.y) : "l"(v));
    return f;
}
__device__ __forceinline__ float ex2(float x) {
    float r;
    asm("ex2.approx.f32 %0, %1;" : "=f"(r) : "f"(x));
    return r;
}

// Pass A v2 (kept from R11, ~122us): u_hat[b,i,d,o], fp16 store, layout [d][o].
// CTA per i. Thread owns 4 W rows; one x LDS stream feeds all 4.
__global__ __launch_bounds__(256) void uhat_kernel(const float* __restrict__ x,
                                                   const float* __restrict__ W) {
    int i = blockIdx.x;
    int t = threadIdx.x;
    int w = t >> 5, l = t & 31;
    __shared__ __align__(16) unsigned long long xs2[B_][ID];   // (xk, xk)
    for (int idx = t; idx < B_ * ID; idx += 256) {
        int b = idx >> 4, k = idx & 15;
        float xv = x[((size_t)b * IC + i) * ID + k];
        xs2[b][k] = pk2(xv, xv);
    }
    __syncthreads();

#pragma unroll
    for (int j = 0; j < 2; j++) {
        int d0 = 8 * j + w;
        int d1 = d0 + 16;
        int o0 = 2 * l;
        const float4* wa0 = (const float4*)(W + ((size_t)i * OCD + (size_t)o0 * OD + d0) * ID);
        const float4* wa1 = (const float4*)(W + ((size_t)i * OCD + (size_t)(o0 + 1) * OD + d0) * ID);
        const float4* wb0 = (const float4*)(W + ((size_t)i * OCD + (size_t)o0 * OD + d1) * ID);
        const float4* wb1 = (const float4*)(W + ((size_t)i * OCD + (size_t)(o0 + 1) * OD + d1) * ID);

        unsigned long long wpA[ID], wpB[ID];
#pragma unroll
        for (int c = 0; c < 4; c++) {
            float4 a0 = wa0[c], a1 = wa1[c];
            wpA[4 * c + 0] = pk2(a0.x, a1.x);
            wpA[4 * c + 1] = pk2(a0.y, a1.y);
            wpA[4 * c + 2] = pk2(a0.z, a1.z);
            wpA[4 * c + 3] = pk2(a0.w, a1.w);
            float4 b0 = wb0[c], b1 = wb1[c];
            wpB[4 * c + 0] = pk2(b0.x, b1.x);
            wpB[4 * c + 1] = pk2(b0.y, b1.y);
            wpB[4 * c + 2] = pk2(b0.z, b1.z);
            wpB[4 * c + 3] = pk2(b0.w, b1.w);
        }

        for (int b = 0; b < B_; b++) {
            const ulonglong2* xp = (const ulonglong2*)xs2[b];
            unsigned long long accA = 0ull, accB = 0ull;   // (0.f, 0.f)
#pragma unroll
            for (int kk = 0; kk < 8; kk++) {
                ulonglong2 xv = xp[kk];
                accA = fma2(wpA[2 * kk],     xv.x, accA);
                accA = fma2(wpA[2 * kk + 1], xv.y, accA);
                accB = fma2(wpB[2 * kk],     xv.x, accB);
                accB = fma2(wpB[2 * kk + 1], xv.y, accB);
            }
            float2 uA = unpk2(accA), uB = unpk2(accB);
            size_t base = ((size_t)b * IC + i) * OCD;
            *(__half2*)(g_uhat + base + (size_t)d0 * OC + o0) = __floats2half2_rn(uA.x, uA.y);
            *(__half2*)(g_uhat + base + (size_t)d1 * OC + o0) = __floats2half2_rn(uB.x, uB.y);
        }
    }
}

__device__ __forceinline__ __half2 h2shfl_xor(__half2 v, int m) {
    unsigned int u = *(unsigned int*)&v;
    u = __shfl_xor_sync(0xffffffffu, u, m);
    return *(__half2*)&u;
}

// Iteration 0: V = 0 -> softmax is exactly uniform (c = 1/64). Plain partial sum.
__global__ __launch_bounds__(128, 8) void routing0_kernel() {
    int chunk = blockIdx.x;
    int b = blockIdx.y;
    int t = threadIdx.x;
    int w = t >> 5, l = t & 31;
    int d8 = l >> 2, oq = l & 3;
    int d = w * 8 + d8;

    float acc[16];
#pragma unroll
    for (int j = 0; j < 16; j++) acc[j] = 0.f;

    for (int ii = 0; ii < 64; ii++) {
        int i = chunk * 64 + ii;
        const uint4* up = (const uint4*)(g_uhat + ((size_t)b * IC + i) * OCD
                                         + (size_t)d * OC + oq * 16);
        uint4 r0 = up[0], r1 = up[1];
        unsigned int Ur[8] = {r0.x, r0.y, r0.z, r0.w, r1.x, r1.y, r1.z, r1.w};
#pragma unroll
        for (int q = 0; q < 8; q++) {
            float2 uf = __half22float2(((__half2*)Ur)[q]);
            acc[2 * q]     += uf.x;
            acc[2 * q + 1] += uf.y;
        }
    }

    __shared__ float sbuf[OCD];
#pragma unroll
    for (int j = 0; j < 16; j++)
        sbuf[(oq * 16 + j) * OD + d] = acc[j] * (1.0f / 64.0f);
    __syncthreads();

    float* sp = g_spart + ((size_t)(b * NSLOT + chunk)) * OCD;
#pragma unroll
    for (int r = 0; r < 16; r++) {
        int p = t + 128 * r;
        sp[p] = sbuf[p];
    }
}

// Routing (iters 1..4) — exact R8 structure; V in smem as two swizzled float
// planes (conflict-free LDS.32), half2 stash, fp32 exp/Z/acc. regs ~64, 8 CTA/SM.
// Grid (32 chunks, 32 b), 128 thr. Warp w owns d in [8w,8w+8); lane: d8=l>>2, oq=l&3.
__global__ __launch_bounds__(128, 8) void routing_kernel() {
    int chunk = blockIdx.x;
    int b = blockIdx.y;
    int t = threadIdx.x;
    int w = t >> 5, l = t & 31;
    int d8 = l >> 2, oq = l & 3;
    int d = w * 8 + d8;

    // Vx plane [0..1024), Vy plane [1024..2048); column swizzled by (dd + 8*(row>>3)) & 31
    __shared__ float Vs[OCD];        // 8 KB, live through the main loop
    __shared__ float stage[OCD];     // 8 KB output staging
    for (int idx = t; idx < 1024; idx += 128) {
        int q = idx >> 5, dd = idx & 31;
        int swc = (dd + 8 * (q >> 3)) & 31;
        Vs[q * 32 + swc]        = g_V[b * OCD + (2 * q) * OD + dd] * LOG2E;
        Vs[1024 + q * 32 + swc] = g_V[b * OCD + (2 * q + 1) * OD + dd] * LOG2E;
    }
    __syncthreads();

    int swc = (d + 8 * oq) & 31;
    __half2 Vh[8];
#pragma unroll
    for (int q = 0; q < 8; q++) {
        int row = oq * 8 + q;
        Vh[q] = __floats2half2_rn(Vs[row * 32 + swc], Vs[1024 + row * 32 + swc]);
    }

    float acc[16];
#pragma unroll
    for (int j = 0; j < 16; j++) acc[j] = 0.f;

    for (int ii = 0; ii < 64; ii++) {
        int i = chunk * 64 + ii;
        const uint4* up = (const uint4*)(g_uhat + ((size_t)b * IC + i) * OCD
                                         + (size_t)d * OC + oq * 16);
        uint4 r0 = up[0], r1 = up[1];
        unsigned int Ur[8] = {r0.x, r0.y, r0.z, r0.w, r1.x, r1.y, r1.z, r1.w};
        __half2* U = (__half2*)Ur;

        // max pass in half2 (any m >= per-i max is softmax-exact)
        __half2 mh = __float2half2_rn(-60000.f);
#pragma unroll
        for (int q = 0; q < 8; q++)
            mh = __hmax2(mh, __hmul2(U[q], Vh[q]));
        mh = __hmax2(mh, h2shfl_xor(mh, 1));
        mh = __hmax2(mh, h2shfl_xor(mh, 2));
        mh = __hmax2(mh, __lowhigh2highlow(mh));
        float m = __low2float(mh);

        // exp pass: fp32 logits from swizzled smem V, MUFU ex2; stash u*e as half2
        float Z = 0.f;
#pragma unroll
        for (int q = 0; q < 8; q++) {
            int row = oq * 8 + q;
            float2 uf = __half22float2(U[q]);
            float e0 = ex2(fmaf(uf.x, Vs[row * 32 + swc], -m));
            float e1 = ex2(fmaf(uf.y, Vs[1024 + row * 32 + swc], -m));
            Z += e0 + e1;
            __half2 th = __floats2half2_rn(uf.x * e0, uf.y * e1);
            U[q] = th;
        }
        Z += __shfl_xor_sync(0xffffffffu, Z, 1);
        Z += __shfl_xor_sync(0xffffffffu, Z, 2);
        float rZ = __fdividef(1.0f, Z);
#pragma unroll
        for (int q = 0; q < 8; q++) {
            float2 tf = __half22float2(U[q]);
            acc[2 * q]     = fmaf(tf.x, rZ, acc[2 * q]);
            acc[2 * q + 1] = fmaf(tf.y, rZ, acc[2 * q + 1]);
        }
    }

#pragma unroll
    for (int j = 0; j < 16; j++)
        stage[(oq * 16 + j) * OD + d] = acc[j];
    __syncthreads();

    // coalesced store of the CTA partial
    float* sp = g_spart + ((size_t)(b * NSLOT + chunk)) * OCD;
#pragma unroll
    for (int r = 0; r < 16; r++) {
        int p = t + 128 * r;
        sp[p] = stage[p];
    }
}

// Reduce 32 fp32 slots, squash over d, update V (+ output on last iter).
__global__ __launch_bounds__(128) void update_kernel(float* __restrict__ out, int is_last) {
    int bo = blockIdx.x;       // 0..2047
    int b = bo >> 6, o = bo & 63;
    int t = threadIdx.x;
    int g = t >> 5, d = t & 31;

    float s = 0.f;
#pragma unroll
    for (int k = 0; k < 8; k++)
        s += g_spart[((size_t)(b * NSLOT + g + 4 * k)) * OCD + o * OD + d];

    __shared__ float red[4][OD];
    red[g][d] = s;
    __syncthreads();

    if (t < 32) {
        float tot = red[0][d] + red[1][d] + red[2][d] + red[3][d];
        float n2 = tot * tot;
#pragma unroll
        for (int k = 16; k > 0; k >>= 1) n2 += __shfl_xor_sync(0xffffffffu, n2, k);
        float factor = n2 / ((1.f + n2) * sqrtf(n2 + 1e-8f));
        float v = factor * tot;
        g_V[b * OCD + o * OD + d] += v;
        if (is_last) out[((size_t)b * OC + o) * OD + d] = v;
    }
}

extern "C" void kernel_launch(void* const* d_in, const int* in_sizes, int n_in,
                              void* d_out, int out_size) {
    const float* x = (const float*)d_in[0];
    const float* W = (const float*)d_in[1];
    if (n_in >= 2 && in_sizes[0] > in_sizes[1]) {  // defensive: x is the smaller input
        const float* tmp = x; x = W; W = tmp;
    }
    float* out = (float*)d_out;

    // launches: 0 init, 1 init, 2 uhat, 3 routing0, 4 update, 5 routing <- ncu -s 5
    init_V<<<128, 256>>>(0);
    init_V<<<128, 256>>>(32768);
    uhat_kernel<<<IC, 256>>>(x, W);
    routing0_kernel<<<dim3(NSLOT, B_), 128>>>();
    update_kernel<<<B_ * OC, 128>>>(out, 0);
    for (int r = 1; r < ITERS; r++) {
        routing_kernel<<<dim3(NSLOT, B_), 128>>>();
        update_kernel<<<B_ * OC, 128>>>(out, r == ITERS - 1);
    }
}